// round 12
// baseline (speedup 1.0000x reference)
#include <cuda_runtime.h>
#include <cuda_fp16.h>
#include <math.h>
#include <stdint.h>

#define FEAT_I 512
#define H_DIM  1024
#define CODE   640
#define CODE_G 320
#define FEAT_G 256
#define B_     8
#define T_     4096
#define N_     (B_ * T_)                  // 32768
#define Q_ELEMS ((size_t)B_ * 512 * T_)   // 16,777,216

#define K2_1 (2 * FEAT_I)    // 1024
#define K2_2 (2 * H_DIM)     // 2048

#define WSCALE     64.0f
#define INV_WSCALE (1.0f / 64.0f)

// margin threshold (approx-logit error ~5e-5 rms; 0.01 = 200 sigma)
#define THR  0.01f
#define CAP  8192

// gemm1 smem: 2 bufs x (2 A-planes + 2 B-planes) x 8KB = 64KB
#define PLANE_SZ   8192
#define B_OFF      16384
#define BUF_STRIDE 32768
#define SMEM_DYN   65536
// gemm2 smem: 2 bufs x (A 8KB + B 8KB) = 32KB
#define SMEM_DYN2  32768

// ---------------------------------------------------------------------------
// Device scratch (allocation-free rule)
// ---------------------------------------------------------------------------
__device__ __half g_xh [(size_t)N_    * K2_1];  // x planes    [m][p*512+k]
__device__ __half g_w1h[(size_t)H_DIM * K2_1];  // (64*W1)^T   [n][p*512+k]
__device__ __half g_hh [(size_t)N_    * K2_2];  // h planes    [m][p*1024+k]
__device__ __half g_w2h[(size_t)CODE  * K2_2];  // (64*W2)^T   [n][p*1024+k]
__device__ float  g_logits[(size_t)N_ * CODE];  // approx perturbed logits
__device__ int    g_idx_arr[(size_t)N_ * 2];    // argmax per (n, g)
__device__ int    g_list[CAP];                  // uncertain (n*2+g) entries
__device__ int    g_count;

// ---------------------------------------------------------------------------
// PTX helpers (arch-agnostic sm_80-class)
// ---------------------------------------------------------------------------
__device__ __forceinline__ uint32_t smem_u32(const void* p) {
    uint32_t a;
    asm("{ .reg .u64 t; cvta.to.shared.u64 t, %1; cvt.u32.u64 %0, t; }" : "=r"(a) : "l"(p));
    return a;
}
__device__ __forceinline__ void cp16(uint32_t saddr, const void* g) {
    asm volatile("cp.async.cg.shared.global [%0], [%1], 16;" :: "r"(saddr), "l"(g));
}
#define CP_COMMIT() asm volatile("cp.async.commit_group;" ::: "memory")
#define CP_WAIT0()  asm volatile("cp.async.wait_group 0;" ::: "memory")
#define CP_WAIT1()  asm volatile("cp.async.wait_group 1;" ::: "memory")

__device__ __forceinline__ void ldsm4(uint32_t& a, uint32_t& b, uint32_t& c, uint32_t& d,
                                      uint32_t addr) {
    asm volatile("ldmatrix.sync.aligned.m8n8.x4.shared.b16 {%0,%1,%2,%3}, [%4];"
                 : "=r"(a), "=r"(b), "=r"(c), "=r"(d) : "r"(addr));
}
__device__ __forceinline__ void mma16816(float* d, const uint32_t* a, uint32_t b0, uint32_t b1) {
    asm volatile("mma.sync.aligned.m16n8k16.row.col.f32.f16.f16.f32 "
                 "{%0,%1,%2,%3},{%4,%5,%6,%7},{%8,%9},{%0,%1,%2,%3};"
                 : "+f"(d[0]), "+f"(d[1]), "+f"(d[2]), "+f"(d[3])
                 : "r"(a[0]), "r"(a[1]), "r"(a[2]), "r"(a[3]), "r"(b0), "r"(b1));
}

__device__ __forceinline__ void split2(float v, __half& hi, __half& lo) {
    hi = __float2half_rn(v);
    lo = __float2half_rn(v - __half2float(hi));
}
__device__ __forceinline__ uint32_t plane_swz(int r, int c) {
    return (uint32_t)(r * 64 + ((c ^ ((r >> 1) & 3)) * 16));
}
__device__ __forceinline__ float gumbelf(float u) {
    return -logf(-logf(u + 1e-10f) + 1e-10f);
}

// ---------------------------------------------------------------------------
// GEMM1 core (R10, proven): 128x128 block, 256 thr, 64x32 warp tiles,
// 3 cross terms over 2 fp16 planes, 2-ahead cp.async pipeline.
// ---------------------------------------------------------------------------
template<int KPLANE>
__device__ __forceinline__ void gemm_core3(const char* __restrict__ Abase,
                                           const char* __restrict__ Bbase,
                                           int tid, uint32_t smb,
                                           float acc[4][4][4]) {
    const int lane = tid & 31, wid = tid >> 5;
    const int warp_m = wid >> 2;     // 0..1
    const int warp_n = wid & 3;      // 0..3
    constexpr int KCH = KPLANE / 32;
    const size_t ROWB = (size_t)KPLANE * 4;   // 2 planes * 2 bytes

    const int cst = tid & 3;
    const int rst = tid >> 2;        // 0..63

    auto issue = [&](int kc, int buf) {
        const uint32_t base = smb + buf * BUF_STRIDE;
#pragma unroll
        for (int p = 0; p < 2; p++) {
            const size_t col = (size_t)(p * KPLANE + kc * 32) * 2 + cst * 16;
#pragma unroll
            for (int i = 0; i < 2; i++) {
                const int r = rst + 64 * i;
                const uint32_t so = plane_swz(r, cst);
                cp16(base + p * PLANE_SZ + so,         Abase + (size_t)r * ROWB + col);
                cp16(base + B_OFF + p * PLANE_SZ + so, Bbase + (size_t)r * ROWB + col);
            }
        }
    };

    issue(0, 0); CP_COMMIT();
    issue(1, 1); CP_COMMIT();

    for (int kc = 0; kc < KCH; kc++) {
        if (kc == KCH - 1) { CP_WAIT0(); } else { CP_WAIT1(); }
        __syncthreads();
        const uint32_t bufb = smb + (kc & 1) * BUF_STRIDE;
#pragma unroll
        for (int kk = 0; kk < 2; kk++) {
            const int lrow = lane & 15;
            const int ch = kk * 2 + (lane >> 4);
            uint32_t afr[4][4], bfr[2][4];

            auto loadA = [&](int pa) {
                const uint32_t bA = bufb + pa * PLANE_SZ;
#pragma unroll
                for (int im = 0; im < 4; im++) {
                    const int r = warp_m * 64 + im * 16 + lrow;
                    ldsm4(afr[im][0], afr[im][1], afr[im][2], afr[im][3],
                          bA + plane_swz(r, ch));
                }
            };
            auto loadB = [&](int pb) {
                const uint32_t bB = bufb + B_OFF + pb * PLANE_SZ;
#pragma unroll
                for (int i2 = 0; i2 < 2; i2++) {
                    const int r = warp_n * 32 + i2 * 16 + lrow;
                    ldsm4(bfr[i2][0], bfr[i2][1], bfr[i2][2], bfr[i2][3],
                          bB + plane_swz(r, ch));
                }
            };
            auto mmas = [&]() {
#pragma unroll
                for (int im = 0; im < 4; im++)
#pragma unroll
                    for (int in = 0; in < 4; in++)
                        mma16816(acc[im][in], afr[im],
                                 bfr[in >> 1][in & 1], bfr[in >> 1][(in & 1) + 2]);
            };

            loadA(0); loadB(0); mmas(); loadB(1); mmas();
            loadA(1); loadB(0); mmas();
        }
        __syncthreads();
        if (kc + 2 < KCH) { issue(kc + 2, kc & 1); CP_COMMIT(); }
    }
    __syncthreads();
}

// ---------------------------------------------------------------------------
// GEMM1: h = relu((x @ 64*W1)/64 + b1) -> split2 -> g_hh  (unchanged R10)
// ---------------------------------------------------------------------------
__global__ __launch_bounds__(256, 2)
void gemm1_mma(const float* __restrict__ b1) {
    extern __shared__ char smem[];
    const uint32_t smb = smem_u32(smem);
    const int tid = threadIdx.x, lane = tid & 31, wid = tid >> 5;
    const int warp_m = wid >> 2, warp_n = wid & 3;
    const int jBase = blockIdx.x * 128;
    const int mBase = blockIdx.y * 128;

    float acc[4][4][4];
#pragma unroll
    for (int i = 0; i < 4; i++)
#pragma unroll
        for (int j = 0; j < 4; j++)
#pragma unroll
            for (int k = 0; k < 4; k++) acc[i][j][k] = 0.f;

    gemm_core3<FEAT_I>((const char*)(g_xh + (size_t)mBase * K2_1),
                       (const char*)(g_w1h + (size_t)jBase * K2_1), tid, smb, acc);

    float bv[4][2];
#pragma unroll
    for (int in = 0; in < 4; in++)
#pragma unroll
        for (int e = 0; e < 2; e++)
            bv[in][e] = __ldg(&b1[jBase + warp_n * 32 + in * 8 + (lane & 3) * 2 + e]);
#pragma unroll
    for (int im = 0; im < 4; im++)
#pragma unroll
        for (int in = 0; in < 4; in++)
#pragma unroll
            for (int q = 0; q < 4; q++) {
                float z = acc[im][in][q] * INV_WSCALE + bv[in][q & 1];
                acc[im][in][q] = z > 0.f ? z : 0.f;
            }

    __half* stage = (__half*)smem;
#pragma unroll
    for (int p = 0; p < 2; p++) {
#pragma unroll
        for (int im = 0; im < 4; im++)
#pragma unroll
            for (int in = 0; in < 4; in++)
#pragma unroll
                for (int rr = 0; rr < 2; rr++) {
                    const int r = warp_m * 64 + im * 16 + (lane >> 2) + rr * 8;
                    const int col = warp_n * 32 + in * 8 + (lane & 3) * 2;
                    __half2 v;
#pragma unroll
                    for (int e = 0; e < 2; e++) {
                        float z = acc[im][in][rr * 2 + e];
                        __half hp = __float2half_rn(z);
                        acc[im][in][rr * 2 + e] = z - __half2float(hp);
                        ((__half*)&v)[e] = hp;
                    }
                    *(__half2*)&stage[r * 128 + col] = v;
                }
        __syncthreads();
#pragma unroll
        for (int i = 0; i < 8; i++) {
            const int id = tid + 256 * i;
            const int r = id >> 4, c4 = id & 15;
            float4 v = *(const float4*)&stage[r * 128 + c4 * 8];
            *(float4*)&g_hh[(size_t)(mBase + r) * K2_2 + p * H_DIM + jBase + c4 * 8] = v;
        }
        __syncthreads();
    }
}

// ---------------------------------------------------------------------------
// GEMM2 (1-term approx): logits ~= (h_hi @ 64*W2_hi)/64 + b2 + gumbel
// 256 thr, 64x32 warp tiles, K = 1024 (plane 0 only).
// ---------------------------------------------------------------------------
__global__ __launch_bounds__(256, 2)
void gemm2_mma(const float* __restrict__ b2, const float* __restrict__ gumbel_u) {
    extern __shared__ char smem[];
    const uint32_t smb = smem_u32(smem);
    const int tid = threadIdx.x, lane = tid & 31, wid = tid >> 5;
    const int warp_m = wid >> 2, warp_n = wid & 3;
    const int jBase = blockIdx.x * 128;
    const int mBase = blockIdx.y * 128;

    const char* Abase = (const char*)(g_hh + (size_t)mBase * K2_2);   // plane 0
    const char* Bbase = (const char*)(g_w2h + (size_t)jBase * K2_2);  // plane 0
    const size_t ROWB = (size_t)K2_2 * 2;   // 4096 bytes

    float acc[4][4][4];
#pragma unroll
    for (int i = 0; i < 4; i++)
#pragma unroll
        for (int j = 0; j < 4; j++)
#pragma unroll
            for (int k = 0; k < 4; k++) acc[i][j][k] = 0.f;

    const int cst = tid & 3;
    const int rst = tid >> 2;    // 0..63
    auto issue = [&](int kc, int buf) {
        const uint32_t base = smb + buf * 16384;
        const size_t col = (size_t)kc * 64 + cst * 16;
#pragma unroll
        for (int i = 0; i < 2; i++) {
            const int r = rst + 64 * i;
            const uint32_t so = plane_swz(r, cst);
            cp16(base + so,        Abase + (size_t)r * ROWB + col);
            cp16(base + 8192 + so, Bbase + (size_t)r * ROWB + col);
        }
    };

    issue(0, 0); CP_COMMIT();
    issue(1, 1); CP_COMMIT();

    const int KCH = H_DIM / 32;   // 32
    for (int kc = 0; kc < KCH; kc++) {
        if (kc == KCH - 1) { CP_WAIT0(); } else { CP_WAIT1(); }
        __syncthreads();
        const uint32_t bufb = smb + (kc & 1) * 16384;
#pragma unroll
        for (int kk = 0; kk < 2; kk++) {
            const int lrow = lane & 15;
            const int ch = kk * 2 + (lane >> 4);
            uint32_t afr[4][4], bfr[2][4];
#pragma unroll
            for (int im = 0; im < 4; im++) {
                const int r = warp_m * 64 + im * 16 + lrow;
                ldsm4(afr[im][0], afr[im][1], afr[im][2], afr[im][3],
                      bufb + plane_swz(r, ch));
            }
#pragma unroll
            for (int i2 = 0; i2 < 2; i2++) {
                const int r = warp_n * 32 + i2 * 16 + lrow;
                ldsm4(bfr[i2][0], bfr[i2][1], bfr[i2][2], bfr[i2][3],
                      bufb + 8192 + plane_swz(r, ch));
            }
#pragma unroll
            for (int im = 0; im < 4; im++)
#pragma unroll
                for (int in = 0; in < 4; in++)
                    mma16816(acc[im][in], afr[im],
                             bfr[in >> 1][in & 1], bfr[in >> 1][(in & 1) + 2]);
        }
        __syncthreads();
        if (kc + 2 < KCH) { issue(kc + 2, kc & 1); CP_COMMIT(); }
    }
    __syncthreads();

    float bv[4][2];
#pragma unroll
    for (int in = 0; in < 4; in++)
#pragma unroll
        for (int e = 0; e < 2; e++)
            bv[in][e] = __ldg(&b2[jBase + warp_n * 32 + in * 8 + (lane & 3) * 2 + e]);

#pragma unroll
    for (int im = 0; im < 4; im++)
#pragma unroll
        for (int in = 0; in < 4; in++)
#pragma unroll
            for (int rr = 0; rr < 2; rr++) {
                const int m = mBase + warp_m * 64 + im * 16 + (lane >> 2) + rr * 8;
                const int j = jBase + warp_n * 32 + in * 8 + (lane & 3) * 2;
                const float2 u = *(const float2*)&gumbel_u[(size_t)m * CODE + j];
                float2 o;
                o.x = acc[im][in][rr * 2 + 0] * INV_WSCALE + bv[in][0] + gumbelf(u.x);
                o.y = acc[im][in][rr * 2 + 1] * INV_WSCALE + bv[in][1] + gumbelf(u.y);
                *(float2*)&g_logits[(size_t)m * CODE + j] = o;
            }
}

// ---------------------------------------------------------------------------
__global__ void reset_count() { g_count = 0; }

// ---------------------------------------------------------------------------
// Argmax + margin: top-1 idx (first-index tiebreak) and top-2 value per
// (n,g); rows with margin < THR go on the uncertain list.
// ---------------------------------------------------------------------------
__global__ __launch_bounds__(256)
void argmax_margin_kernel() {
    const int t0 = blockIdx.x * 32;
    const int b  = blockIdx.y;
    const int g  = blockIdx.z;
    const int tid = threadIdx.x, lane = tid & 31, w = tid >> 5;

#pragma unroll
    for (int rr = 0; rr < 4; rr++) {
        const int tl = w * 4 + rr;
        const int n  = b * T_ + t0 + tl;
        const float* lp = g_logits + (size_t)n * CODE + g * CODE_G;
        float v1 = -INFINITY, v2 = -INFINITY;
        int   i1 = 0;
        for (int c = lane; c < CODE_G; c += 32) {
            float v = lp[c];
            if (v > v1) { v2 = v1; v1 = v; i1 = c; }
            else if (v > v2) { v2 = v; }
        }
#pragma unroll
        for (int off = 16; off; off >>= 1) {
            float ov1 = __shfl_down_sync(0xffffffffu, v1, off);
            int   oi1 = __shfl_down_sync(0xffffffffu, i1, off);
            float ov2 = __shfl_down_sync(0xffffffffu, v2, off);
            if (ov1 > v1 || (ov1 == v1 && oi1 < i1)) {
                v2 = fmaxf(fmaxf(v2, ov2), v1);
                v1 = ov1; i1 = oi1;
            } else {
                v2 = fmaxf(fmaxf(v2, ov2), ov1);
            }
        }
        if (lane == 0) {
            const int n2 = n * 2 + g;
            g_idx_arr[n2] = i1;
            if (v1 - v2 < THR) {
                int pos = atomicAdd(&g_count, 1);
                if (pos < CAP) g_list[pos] = n2;
            }
        }
    }
}

// ---------------------------------------------------------------------------
// Refine: exact fp32 recompute of the 320 perturbed logits for each
// uncertain (n,g), using full 2-plane h and 2-plane W2 (reconstructed fp32).
// 4 entries per CTA, 128 threads (4 warps x 80 codes).
// ---------------------------------------------------------------------------
__global__ __launch_bounds__(128)
void refine_kernel(const float* __restrict__ b2, const float* __restrict__ gumbel_u) {
    __shared__ float sh[4][1024];
    __shared__ int   s_ent[4];
    __shared__ float s_v[4][4];
    __shared__ int   s_i[4][4];

    const int tid = threadIdx.x, lane = tid & 31, w = tid >> 5;
    const int cnt = min(g_count, CAP);
    const int base = blockIdx.x * 4;
    if (base >= cnt) return;

    if (tid < 4)
        s_ent[tid] = (base + tid < cnt) ? g_list[base + tid] : -1;
    __syncthreads();

    // load h rows (hi + lo, fp32)
#pragma unroll
    for (int e = 0; e < 4; e++) {
        const int ent = s_ent[e];
        const int n = (ent >= 0) ? (ent >> 1) : 0;
        const __half* hr = g_hh + (size_t)n * K2_2;
        for (int k = tid; k < H_DIM; k += 128)
            sh[e][k] = __half2float(hr[k]) + __half2float(hr[H_DIM + k]);
    }
    __syncthreads();

    // each warp: 80 codes; per code, fp32 dot vs all 4 entries
    float bv1[4] = {-INFINITY, -INFINITY, -INFINITY, -INFINITY};
    int   bi1[4] = {0, 0, 0, 0};

    for (int j = 0; j < 80; j++) {
        const int c = w * 80 + j;
        float accv[4] = {0.f, 0.f, 0.f, 0.f};
#pragma unroll
        for (int e = 0; e < 4; e++) {
            const int ent = s_ent[e];
            if (ent < 0) continue;
            const int gg = ent & 1;
            const __half* wrow = g_w2h + (size_t)(gg * CODE_G + c) * K2_2;
            float a = 0.f;
            for (int it = 0; it < 16; it++) {
                const int k = it * 64 + lane * 2;
                __half2 hi = *(const __half2*)&wrow[k];
                __half2 lo = *(const __half2*)&wrow[H_DIM + k];
                float w0 = __half2float(hi.x) + __half2float(lo.x);
                float w1 = __half2float(hi.y) + __half2float(lo.y);
                a += sh[e][k] * w0 + sh[e][k + 1] * w1;
            }
            accv[e] = a;
        }
        // reduce each acc across the warp
#pragma unroll
        for (int e = 0; e < 4; e++) {
#pragma unroll
            for (int off = 16; off; off >>= 1)
                accv[e] += __shfl_down_sync(0xffffffffu, accv[e], off);
        }
        if (lane == 0) {
#pragma unroll
            for (int e = 0; e < 4; e++) {
                const int ent = s_ent[e];
                if (ent < 0) continue;
                const int n = ent >> 1, gg = ent & 1;
                const int col = gg * CODE_G + c;
                float z = accv[e] * INV_WSCALE + b2[col]
                          + gumbelf(gumbel_u[(size_t)n * CODE + col]);
                if (z > bv1[e]) { bv1[e] = z; bi1[e] = c; }   // ascending j: strict >
            }
        }
    }
    if (lane == 0) {
#pragma unroll
        for (int e = 0; e < 4; e++) { s_v[w][e] = bv1[e]; s_i[w][e] = bi1[e]; }
    }
    __syncthreads();
    if (tid < 4) {
        const int ent = s_ent[tid];
        if (ent >= 0) {
            float v = -INFINITY; int idx = 0;
            for (int ww = 0; ww < 4; ww++)       // ascending code blocks: strict >
                if (s_v[ww][tid] > v) { v = s_v[ww][tid]; idx = s_i[ww][tid]; }
            g_idx_arr[ent] = idx;
        }
    }
}

// ---------------------------------------------------------------------------
// Gather: read final g_idx_arr, write q (codebook rows, t-coalesced) + idx.
// ---------------------------------------------------------------------------
__global__ __launch_bounds__(256)
void gather_kernel(const float* __restrict__ codebook, float* __restrict__ out) {
    const int t0 = blockIdx.x * 32;
    const int b  = blockIdx.y;
    const int g  = blockIdx.z;
    __shared__ int s_idx[32];

    const int tid = threadIdx.x;
    if (tid < 32) {
        const int n = b * T_ + t0 + tid;
        const int id = g_idx_arr[n * 2 + g];
        s_idx[tid] = id;
        out[Q_ELEMS + (size_t)n * 2 + g] = (float)id;
    }
    __syncthreads();

    const int tx = tid & 31, fy = tid >> 5;
    const int idx = s_idx[tx];
    const float* cbrow = codebook + ((size_t)g * CODE_G + idx) * FEAT_G;
    float* outb = out + ((size_t)b * 512 + g * FEAT_G) * T_ + t0;
    for (int f = fy; f < FEAT_G; f += 8)
        outb[(size_t)f * T_ + tx] = cbrow[f];
}

// ---------------------------------------------------------------------------
// Conversion kernels (unchanged R10)
// ---------------------------------------------------------------------------
__global__ __launch_bounds__(256)
void conv_x_kernel(const float* __restrict__ series) {
    __shared__ float s[32][33];
    const int k0 = blockIdx.x * 32, t0 = blockIdx.y * 32, b = blockIdx.z;
    const int tx = threadIdx.x, ty = threadIdx.y;
#pragma unroll
    for (int i = 0; i < 4; i++) {
        int kk = ty + 8 * i;
        s[kk][tx] = series[((size_t)b * FEAT_I + k0 + kk) * T_ + t0 + tx];
    }
    __syncthreads();
#pragma unroll
    for (int i = 0; i < 4; i++) {
        int tt = ty + 8 * i;
        int m = b * T_ + t0 + tt;
        __half hi, lo;
        split2(s[tx][tt], hi, lo);
        __half* row = g_xh + (size_t)m * K2_1;
        row[0 * FEAT_I + k0 + tx] = hi;
        row[1 * FEAT_I + k0 + tx] = lo;
    }
}

__global__ __launch_bounds__(256)
void conv_w1_kernel(const float* __restrict__ W1) {
    __shared__ float s[32][33];
    const int k0 = blockIdx.x * 32, n0 = blockIdx.y * 32;
    const int tx = threadIdx.x, ty = threadIdx.y;
#pragma unroll
    for (int i = 0; i < 4; i++) {
        int kk = ty + 8 * i;
        s[kk][tx] = W1[(size_t)(k0 + kk) * H_DIM + n0 + tx];
    }
    __syncthreads();
#pragma unroll
    for (int i = 0; i < 4; i++) {
        int nn = ty + 8 * i;
        __half hi, lo;
        split2(s[tx][nn] * WSCALE, hi, lo);
        __half* row = g_w1h + (size_t)(n0 + nn) * K2_1;
        row[0 * FEAT_I + k0 + tx] = hi;
        row[1 * FEAT_I + k0 + tx] = lo;
    }
}

__global__ __launch_bounds__(256)
void conv_w2_kernel(const float* __restrict__ W2) {
    __shared__ float s[32][33];
    const int k0 = blockIdx.x * 32, n0 = blockIdx.y * 32;
    const int tx = threadIdx.x, ty = threadIdx.y;
#pragma unroll
    for (int i = 0; i < 4; i++) {
        int kk = ty + 8 * i;
        s[kk][tx] = W2[(size_t)(k0 + kk) * CODE + n0 + tx];
    }
    __syncthreads();
#pragma unroll
    for (int i = 0; i < 4; i++) {
        int nn = ty + 8 * i;
        __half hi, lo;
        split2(s[tx][nn] * WSCALE, hi, lo);
        __half* row = g_w2h + (size_t)(n0 + nn) * K2_2;
        row[0 * H_DIM + k0 + tx] = hi;
        row[1 * H_DIM + k0 + tx] = lo;
    }
}

// ---------------------------------------------------------------------------
extern "C" void kernel_launch(void* const* d_in, const int* in_sizes, int n_in,
                              void* d_out, int out_size)
{
    const float* series   = (const float*)d_in[0];
    const float* gumbel_u = (const float*)d_in[1];
    const float* W1       = (const float*)d_in[2];
    const float* b1       = (const float*)d_in[3];
    const float* W2       = (const float*)d_in[4];
    const float* b2       = (const float*)d_in[5];
    const float* codebook = (const float*)d_in[6];
    float* out = (float*)d_out;

    cudaFuncSetAttribute(gemm1_mma, cudaFuncAttributeMaxDynamicSharedMemorySize, SMEM_DYN);
    cudaFuncSetAttribute(gemm2_mma, cudaFuncAttributeMaxDynamicSharedMemorySize, SMEM_DYN2);

    conv_x_kernel <<<dim3(FEAT_I / 32, T_ / 32, B_), dim3(32, 8)>>>(series);
    conv_w1_kernel<<<dim3(FEAT_I / 32, H_DIM / 32),  dim3(32, 8)>>>(W1);
    conv_w2_kernel<<<dim3(H_DIM / 32, CODE / 32),    dim3(32, 8)>>>(W2);

    gemm1_mma<<<dim3(H_DIM / 128, N_ / 128), 256, SMEM_DYN>>>(b1);
    gemm2_mma<<<dim3(CODE / 128,  N_ / 128), 256, SMEM_DYN2>>>(b2, gumbel_u);

    reset_count<<<1, 1>>>();
    argmax_margin_kernel<<<dim3(T_ / 32, B_, 2), 256>>>();
    refine_kernel<<<CAP / 4, 128>>>(b2, gumbel_u);
    gather_kernel<<<dim3(T_ / 32, B_, 2), 256>>>(codebook, out);
}

// round 13
// speedup vs baseline: 1.8507x; 1.8507x over previous
#include <cuda_runtime.h>
#include <cuda_fp16.h>
#include <math.h>
#include <stdint.h>

#define FEAT_I 512
#define H_DIM  1024
#define CODE   640
#define CODE_G 320
#define FEAT_G 256
#define B_     8
#define T_     4096
#define N_     (B_ * T_)                  // 32768
#define Q_ELEMS ((size_t)B_ * 512 * T_)   // 16,777,216

#define K2_1 (2 * FEAT_I)    // 1024
#define K2_2 (2 * H_DIM)     // 2048

#define WSCALE     64.0f
#define INV_WSCALE (1.0f / 64.0f)

// margin threshold: approx-logit error ~2e-4 rms (max ~2e-3); 0.01 listing
// threshold is >5x max error; candidate threshold 0.02 is >10x.
#define THR  0.01f
#define CAP  8192

// gemm1 smem: 2 bufs x (2 A-planes + 2 B-planes) x 8KB = 64KB
#define PLANE_SZ   8192
#define B_OFF      16384
#define BUF_STRIDE 32768
#define SMEM_DYN   65536
// gemm2 smem: 2 bufs x (A 8KB + B 8KB) = 32KB
#define SMEM_DYN2  32768

// ---------------------------------------------------------------------------
// Device scratch (allocation-free rule)
// ---------------------------------------------------------------------------
__device__ __half g_xh [(size_t)N_    * K2_1];  // x planes    [m][p*512+k]
__device__ __half g_w1h[(size_t)H_DIM * K2_1];  // (64*W1)^T   [n][p*512+k]
__device__ __half g_hh [(size_t)N_    * K2_2];  // h planes    [m][p*1024+k]
__device__ __half g_w2h[(size_t)CODE  * K2_2];  // (64*W2)^T   [n][p*1024+k]
__device__ float  g_logits[(size_t)N_ * CODE];  // approx perturbed logits
__device__ int    g_idx_arr[(size_t)N_ * 2];    // argmax per (n, g)
__device__ int    g_list[CAP];                  // uncertain (n*2+g) entries
__device__ int    g_count;

// ---------------------------------------------------------------------------
// PTX helpers (arch-agnostic sm_80-class)
// ---------------------------------------------------------------------------
__device__ __forceinline__ uint32_t smem_u32(const void* p) {
    uint32_t a;
    asm("{ .reg .u64 t; cvta.to.shared.u64 t, %1; cvt.u32.u64 %0, t; }" : "=r"(a) : "l"(p));
    return a;
}
__device__ __forceinline__ void cp16(uint32_t saddr, const void* g) {
    asm volatile("cp.async.cg.shared.global [%0], [%1], 16;" :: "r"(saddr), "l"(g));
}
#define CP_COMMIT() asm volatile("cp.async.commit_group;" ::: "memory")
#define CP_WAIT0()  asm volatile("cp.async.wait_group 0;" ::: "memory")
#define CP_WAIT1()  asm volatile("cp.async.wait_group 1;" ::: "memory")

__device__ __forceinline__ void ldsm4(uint32_t& a, uint32_t& b, uint32_t& c, uint32_t& d,
                                      uint32_t addr) {
    asm volatile("ldmatrix.sync.aligned.m8n8.x4.shared.b16 {%0,%1,%2,%3}, [%4];"
                 : "=r"(a), "=r"(b), "=r"(c), "=r"(d) : "r"(addr));
}
__device__ __forceinline__ void mma16816(float* d, const uint32_t* a, uint32_t b0, uint32_t b1) {
    asm volatile("mma.sync.aligned.m16n8k16.row.col.f32.f16.f16.f32 "
                 "{%0,%1,%2,%3},{%4,%5,%6,%7},{%8,%9},{%0,%1,%2,%3};"
                 : "+f"(d[0]), "+f"(d[1]), "+f"(d[2]), "+f"(d[3])
                 : "r"(a[0]), "r"(a[1]), "r"(a[2]), "r"(a[3]), "r"(b0), "r"(b1));
}

__device__ __forceinline__ void split2(float v, __half& hi, __half& lo) {
    hi = __float2half_rn(v);
    lo = __float2half_rn(v - __half2float(hi));
}
__device__ __forceinline__ uint32_t plane_swz(int r, int c) {
    return (uint32_t)(r * 64 + ((c ^ ((r >> 1) & 3)) * 16));
}
__device__ __forceinline__ float gumbelf(float u) {
    return -logf(-logf(u + 1e-10f) + 1e-10f);
}

// ---------------------------------------------------------------------------
// GEMM1 core (R10, proven): 128x128 block, 256 thr, 64x32 warp tiles,
// 3 cross terms over 2 fp16 planes, 2-ahead cp.async pipeline.
// ---------------------------------------------------------------------------
template<int KPLANE>
__device__ __forceinline__ void gemm_core3(const char* __restrict__ Abase,
                                           const char* __restrict__ Bbase,
                                           int tid, uint32_t smb,
                                           float acc[4][4][4]) {
    const int lane = tid & 31, wid = tid >> 5;
    const int warp_m = wid >> 2;     // 0..1
    const int warp_n = wid & 3;      // 0..3
    constexpr int KCH = KPLANE / 32;
    const size_t ROWB = (size_t)KPLANE * 4;   // 2 planes * 2 bytes

    const int cst = tid & 3;
    const int rst = tid >> 2;        // 0..63

    auto issue = [&](int kc, int buf) {
        const uint32_t base = smb + buf * BUF_STRIDE;
#pragma unroll
        for (int p = 0; p < 2; p++) {
            const size_t col = (size_t)(p * KPLANE + kc * 32) * 2 + cst * 16;
#pragma unroll
            for (int i = 0; i < 2; i++) {
                const int r = rst + 64 * i;
                const uint32_t so = plane_swz(r, cst);
                cp16(base + p * PLANE_SZ + so,         Abase + (size_t)r * ROWB + col);
                cp16(base + B_OFF + p * PLANE_SZ + so, Bbase + (size_t)r * ROWB + col);
            }
        }
    };

    issue(0, 0); CP_COMMIT();
    issue(1, 1); CP_COMMIT();

    for (int kc = 0; kc < KCH; kc++) {
        if (kc == KCH - 1) { CP_WAIT0(); } else { CP_WAIT1(); }
        __syncthreads();
        const uint32_t bufb = smb + (kc & 1) * BUF_STRIDE;
#pragma unroll
        for (int kk = 0; kk < 2; kk++) {
            const int lrow = lane & 15;
            const int ch = kk * 2 + (lane >> 4);
            uint32_t afr[4][4], bfr[2][4];

            auto loadA = [&](int pa) {
                const uint32_t bA = bufb + pa * PLANE_SZ;
#pragma unroll
                for (int im = 0; im < 4; im++) {
                    const int r = warp_m * 64 + im * 16 + lrow;
                    ldsm4(afr[im][0], afr[im][1], afr[im][2], afr[im][3],
                          bA + plane_swz(r, ch));
                }
            };
            auto loadB = [&](int pb) {
                const uint32_t bB = bufb + B_OFF + pb * PLANE_SZ;
#pragma unroll
                for (int i2 = 0; i2 < 2; i2++) {
                    const int r = warp_n * 32 + i2 * 16 + lrow;
                    ldsm4(bfr[i2][0], bfr[i2][1], bfr[i2][2], bfr[i2][3],
                          bB + plane_swz(r, ch));
                }
            };
            auto mmas = [&]() {
#pragma unroll
                for (int im = 0; im < 4; im++)
#pragma unroll
                    for (int in = 0; in < 4; in++)
                        mma16816(acc[im][in], afr[im],
                                 bfr[in >> 1][in & 1], bfr[in >> 1][(in & 1) + 2]);
            };

            loadA(0); loadB(0); mmas(); loadB(1); mmas();
            loadA(1); loadB(0); mmas();
        }
        __syncthreads();
        if (kc + 2 < KCH) { issue(kc + 2, kc & 1); CP_COMMIT(); }
    }
    __syncthreads();
}

// ---------------------------------------------------------------------------
// GEMM1: h = relu((x @ 64*W1)/64 + b1) -> split2 -> g_hh  (unchanged R10)
// ---------------------------------------------------------------------------
__global__ __launch_bounds__(256, 2)
void gemm1_mma(const float* __restrict__ b1) {
    extern __shared__ char smem[];
    const uint32_t smb = smem_u32(smem);
    const int tid = threadIdx.x, lane = tid & 31, wid = tid >> 5;
    const int warp_m = wid >> 2, warp_n = wid & 3;
    const int jBase = blockIdx.x * 128;
    const int mBase = blockIdx.y * 128;

    float acc[4][4][4];
#pragma unroll
    for (int i = 0; i < 4; i++)
#pragma unroll
        for (int j = 0; j < 4; j++)
#pragma unroll
            for (int k = 0; k < 4; k++) acc[i][j][k] = 0.f;

    gemm_core3<FEAT_I>((const char*)(g_xh + (size_t)mBase * K2_1),
                       (const char*)(g_w1h + (size_t)jBase * K2_1), tid, smb, acc);

    float bv[4][2];
#pragma unroll
    for (int in = 0; in < 4; in++)
#pragma unroll
        for (int e = 0; e < 2; e++)
            bv[in][e] = __ldg(&b1[jBase + warp_n * 32 + in * 8 + (lane & 3) * 2 + e]);
#pragma unroll
    for (int im = 0; im < 4; im++)
#pragma unroll
        for (int in = 0; in < 4; in++)
#pragma unroll
            for (int q = 0; q < 4; q++) {
                float z = acc[im][in][q] * INV_WSCALE + bv[in][q & 1];
                acc[im][in][q] = z > 0.f ? z : 0.f;
            }

    __half* stage = (__half*)smem;
#pragma unroll
    for (int p = 0; p < 2; p++) {
#pragma unroll
        for (int im = 0; im < 4; im++)
#pragma unroll
            for (int in = 0; in < 4; in++)
#pragma unroll
                for (int rr = 0; rr < 2; rr++) {
                    const int r = warp_m * 64 + im * 16 + (lane >> 2) + rr * 8;
                    const int col = warp_n * 32 + in * 8 + (lane & 3) * 2;
                    __half2 v;
#pragma unroll
                    for (int e = 0; e < 2; e++) {
                        float z = acc[im][in][rr * 2 + e];
                        __half hp = __float2half_rn(z);
                        acc[im][in][rr * 2 + e] = z - __half2float(hp);
                        ((__half*)&v)[e] = hp;
                    }
                    *(__half2*)&stage[r * 128 + col] = v;
                }
        __syncthreads();
#pragma unroll
        for (int i = 0; i < 8; i++) {
            const int id = tid + 256 * i;
            const int r = id >> 4, c4 = id & 15;
            float4 v = *(const float4*)&stage[r * 128 + c4 * 8];
            *(float4*)&g_hh[(size_t)(mBase + r) * K2_2 + p * H_DIM + jBase + c4 * 8] = v;
        }
        __syncthreads();
    }
}

// ---------------------------------------------------------------------------
// GEMM2 (1-term approx): logits ~= (h_hi @ 64*W2_hi)/64 + b2 + gumbel
// ---------------------------------------------------------------------------
__global__ __launch_bounds__(256, 2)
void gemm2_mma(const float* __restrict__ b2, const float* __restrict__ gumbel_u) {
    extern __shared__ char smem[];
    const uint32_t smb = smem_u32(smem);
    const int tid = threadIdx.x, lane = tid & 31, wid = tid >> 5;
    const int warp_m = wid >> 2, warp_n = wid & 3;
    const int jBase = blockIdx.x * 128;
    const int mBase = blockIdx.y * 128;

    const char* Abase = (const char*)(g_hh + (size_t)mBase * K2_2);   // plane 0
    const char* Bbase = (const char*)(g_w2h + (size_t)jBase * K2_2);  // plane 0
    const size_t ROWB = (size_t)K2_2 * 2;   // 4096 bytes

    float acc[4][4][4];
#pragma unroll
    for (int i = 0; i < 4; i++)
#pragma unroll
        for (int j = 0; j < 4; j++)
#pragma unroll
            for (int k = 0; k < 4; k++) acc[i][j][k] = 0.f;

    const int cst = tid & 3;
    const int rst = tid >> 2;    // 0..63
    auto issue = [&](int kc, int buf) {
        const uint32_t base = smb + buf * 16384;
        const size_t col = (size_t)kc * 64 + cst * 16;
#pragma unroll
        for (int i = 0; i < 2; i++) {
            const int r = rst + 64 * i;
            const uint32_t so = plane_swz(r, cst);
            cp16(base + so,        Abase + (size_t)r * ROWB + col);
            cp16(base + 8192 + so, Bbase + (size_t)r * ROWB + col);
        }
    };

    issue(0, 0); CP_COMMIT();
    issue(1, 1); CP_COMMIT();

    const int KCH = H_DIM / 32;   // 32
    for (int kc = 0; kc < KCH; kc++) {
        if (kc == KCH - 1) { CP_WAIT0(); } else { CP_WAIT1(); }
        __syncthreads();
        const uint32_t bufb = smb + (kc & 1) * 16384;
#pragma unroll
        for (int kk = 0; kk < 2; kk++) {
            const int lrow = lane & 15;
            const int ch = kk * 2 + (lane >> 4);
            uint32_t afr[4][4], bfr[2][4];
#pragma unroll
            for (int im = 0; im < 4; im++) {
                const int r = warp_m * 64 + im * 16 + lrow;
                ldsm4(afr[im][0], afr[im][1], afr[im][2], afr[im][3],
                      bufb + plane_swz(r, ch));
            }
#pragma unroll
            for (int i2 = 0; i2 < 2; i2++) {
                const int r = warp_n * 32 + i2 * 16 + lrow;
                ldsm4(bfr[i2][0], bfr[i2][1], bfr[i2][2], bfr[i2][3],
                      bufb + 8192 + plane_swz(r, ch));
            }
#pragma unroll
            for (int im = 0; im < 4; im++)
#pragma unroll
                for (int in = 0; in < 4; in++)
                    mma16816(acc[im][in], afr[im],
                             bfr[in >> 1][in & 1], bfr[in >> 1][(in & 1) + 2]);
        }
        __syncthreads();
        if (kc + 2 < KCH) { issue(kc + 2, kc & 1); CP_COMMIT(); }
    }
    __syncthreads();

    float bv[4][2];
#pragma unroll
    for (int in = 0; in < 4; in++)
#pragma unroll
        for (int e = 0; e < 2; e++)
            bv[in][e] = __ldg(&b2[jBase + warp_n * 32 + in * 8 + (lane & 3) * 2 + e]);

#pragma unroll
    for (int im = 0; im < 4; im++)
#pragma unroll
        for (int in = 0; in < 4; in++)
#pragma unroll
            for (int rr = 0; rr < 2; rr++) {
                const int m = mBase + warp_m * 64 + im * 16 + (lane >> 2) + rr * 8;
                const int j = jBase + warp_n * 32 + in * 8 + (lane & 3) * 2;
                const float2 u = *(const float2*)&gumbel_u[(size_t)m * CODE + j];
                float2 o;
                o.x = acc[im][in][rr * 2 + 0] * INV_WSCALE + bv[in][0] + gumbelf(u.x);
                o.y = acc[im][in][rr * 2 + 1] * INV_WSCALE + bv[in][1] + gumbelf(u.y);
                *(float2*)&g_logits[(size_t)m * CODE + j] = o;
            }
}

// ---------------------------------------------------------------------------
__global__ void reset_count() { g_count = 0; }

// ---------------------------------------------------------------------------
// Argmax + margin (validated in R12): top-1 idx + top-2 value per (n,g);
// rows with margin < THR go on the uncertain list.
// ---------------------------------------------------------------------------
__global__ __launch_bounds__(256)
void argmax_margin_kernel() {
    const int t0 = blockIdx.x * 32;
    const int b  = blockIdx.y;
    const int g  = blockIdx.z;
    const int tid = threadIdx.x, lane = tid & 31, w = tid >> 5;

#pragma unroll
    for (int rr = 0; rr < 4; rr++) {
        const int tl = w * 4 + rr;
        const int n  = b * T_ + t0 + tl;
        const float* lp = g_logits + (size_t)n * CODE + g * CODE_G;
        float v1 = -INFINITY, v2 = -INFINITY;
        int   i1 = 0;
        for (int c = lane; c < CODE_G; c += 32) {
            float v = lp[c];
            if (v > v1) { v2 = v1; v1 = v; i1 = c; }
            else if (v > v2) { v2 = v; }
        }
#pragma unroll
        for (int off = 16; off; off >>= 1) {
            float ov1 = __shfl_down_sync(0xffffffffu, v1, off);
            int   oi1 = __shfl_down_sync(0xffffffffu, i1, off);
            float ov2 = __shfl_down_sync(0xffffffffu, v2, off);
            if (ov1 > v1 || (ov1 == v1 && oi1 < i1)) {
                v2 = fmaxf(fmaxf(v2, ov2), v1);
                v1 = ov1; i1 = oi1;
            } else {
                v2 = fmaxf(fmaxf(v2, ov2), ov1);
            }
        }
        if (lane == 0) {
            const int n2 = n * 2 + g;
            g_idx_arr[n2] = i1;
            if (v1 - v2 < THR) {
                int pos = atomicAdd(&g_count, 1);
                if (pos < CAP) g_list[pos] = n2;
            }
        }
    }
}

// ---------------------------------------------------------------------------
// Refine v2 (candidate-restricted): one warp per uncertain entry.
// Rescan the 320 approx logits; codes within 2*THR of the approx max
// (typically ~2) get an exact fp32 recompute; ascending-index strict-> keeps
// first-max tiebreak. Non-candidates provably cannot be the exact argmax.
// ---------------------------------------------------------------------------
__global__ __launch_bounds__(128)
void refine_kernel(const float* __restrict__ b2, const float* __restrict__ gumbel_u) {
    const int tid = threadIdx.x, lane = tid & 31, w = tid >> 5;
    const int cnt = min(g_count, CAP);
    const int widx = blockIdx.x * 4 + w;
    if (widx >= cnt) return;

    const int ent = g_list[widx];
    const int n = ent >> 1, g = ent & 1;

    // approx logits for this row: 10 per lane (code c = 32*j + lane)
    const float* lp = g_logits + (size_t)n * CODE + g * CODE_G;
    float z[10];
#pragma unroll
    for (int j = 0; j < 10; j++) z[j] = lp[32 * j + lane];

    float v1 = -INFINITY;
#pragma unroll
    for (int j = 0; j < 10; j++) v1 = fmaxf(v1, z[j]);
#pragma unroll
    for (int off = 16; off; off >>= 1)
        v1 = fmaxf(v1, __shfl_xor_sync(0xffffffffu, v1, off));
    const float thresh = v1 - 2.0f * THR;

    // preload h (hi+lo reconstructed fp32); lane owns k = 2*lane + 64*jj
    float2 hv[16];
    const __half* hr = g_hh + (size_t)n * K2_2;
#pragma unroll
    for (int jj = 0; jj < 16; jj++) {
        const int k = 2 * lane + 64 * jj;
        __half2 hi = *(const __half2*)&hr[k];
        __half2 lo = *(const __half2*)&hr[H_DIM + k];
        hv[jj].x = __half2float(hi.x) + __half2float(lo.x);
        hv[jj].y = __half2float(hi.y) + __half2float(lo.y);
    }

    float best = -INFINITY;
    int   bidx = 0;
    for (int j = 0; j < 10; j++) {
        unsigned bits = __ballot_sync(0xffffffffu, z[j] >= thresh);
        while (bits) {
            const int i = __ffs(bits) - 1;
            bits &= bits - 1;
            const int c = 32 * j + i;                 // ascending within row
            const __half* wrow = g_w2h + (size_t)(g * CODE_G + c) * K2_2;
            float a = 0.f;
#pragma unroll
            for (int jj = 0; jj < 16; jj++) {
                const int k = 2 * lane + 64 * jj;
                __half2 hi = *(const __half2*)&wrow[k];
                __half2 lo = *(const __half2*)&wrow[H_DIM + k];
                a += hv[jj].x * (__half2float(hi.x) + __half2float(lo.x))
                   + hv[jj].y * (__half2float(hi.y) + __half2float(lo.y));
            }
#pragma unroll
            for (int off = 16; off; off >>= 1)
                a += __shfl_xor_sync(0xffffffffu, a, off);
            const int col = g * CODE_G + c;
            const float z_ex = a * INV_WSCALE + b2[col]
                               + gumbelf(gumbel_u[(size_t)n * CODE + col]);
            if (z_ex > best) { best = z_ex; bidx = c; }
        }
    }
    if (lane == 0) g_idx_arr[ent] = bidx;
}

// ---------------------------------------------------------------------------
// Gather: read final g_idx_arr, write q (codebook rows, t-coalesced) + idx.
// ---------------------------------------------------------------------------
__global__ __launch_bounds__(256)
void gather_kernel(const float* __restrict__ codebook, float* __restrict__ out) {
    const int t0 = blockIdx.x * 32;
    const int b  = blockIdx.y;
    const int g  = blockIdx.z;
    __shared__ int s_idx[32];

    const int tid = threadIdx.x;
    if (tid < 32) {
        const int n = b * T_ + t0 + tid;
        const int id = g_idx_arr[n * 2 + g];
        s_idx[tid] = id;
        out[Q_ELEMS + (size_t)n * 2 + g] = (float)id;
    }
    __syncthreads();

    const int tx = tid & 31, fy = tid >> 5;
    const int idx = s_idx[tx];
    const float* cbrow = codebook + ((size_t)g * CODE_G + idx) * FEAT_G;
    float* outb = out + ((size_t)b * 512 + g * FEAT_G) * T_ + t0;
    for (int f = fy; f < FEAT_G; f += 8)
        outb[(size_t)f * T_ + tx] = cbrow[f];
}

// ---------------------------------------------------------------------------
// Conversion kernels (unchanged R10)
// ---------------------------------------------------------------------------
__global__ __launch_bounds__(256)
void conv_x_kernel(const float* __restrict__ series) {
    __shared__ float s[32][33];
    const int k0 = blockIdx.x * 32, t0 = blockIdx.y * 32, b = blockIdx.z;
    const int tx = threadIdx.x, ty = threadIdx.y;
#pragma unroll
    for (int i = 0; i < 4; i++) {
        int kk = ty + 8 * i;
        s[kk][tx] = series[((size_t)b * FEAT_I + k0 + kk) * T_ + t0 + tx];
    }
    __syncthreads();
#pragma unroll
    for (int i = 0; i < 4; i++) {
        int tt = ty + 8 * i;
        int m = b * T_ + t0 + tt;
        __half hi, lo;
        split2(s[tx][tt], hi, lo);
        __half* row = g_xh + (size_t)m * K2_1;
        row[0 * FEAT_I + k0 + tx] = hi;
        row[1 * FEAT_I + k0 + tx] = lo;
    }
}

__global__ __launch_bounds__(256)
void conv_w1_kernel(const float* __restrict__ W1) {
    __shared__ float s[32][33];
    const int k0 = blockIdx.x * 32, n0 = blockIdx.y * 32;
    const int tx = threadIdx.x, ty = threadIdx.y;
#pragma unroll
    for (int i = 0; i < 4; i++) {
        int kk = ty + 8 * i;
        s[kk][tx] = W1[(size_t)(k0 + kk) * H_DIM + n0 + tx];
    }
    __syncthreads();
#pragma unroll
    for (int i = 0; i < 4; i++) {
        int nn = ty + 8 * i;
        __half hi, lo;
        split2(s[tx][nn] * WSCALE, hi, lo);
        __half* row = g_w1h + (size_t)(n0 + nn) * K2_1;
        row[0 * FEAT_I + k0 + tx] = hi;
        row[1 * FEAT_I + k0 + tx] = lo;
    }
}

__global__ __launch_bounds__(256)
void conv_w2_kernel(const float* __restrict__ W2) {
    __shared__ float s[32][33];
    const int k0 = blockIdx.x * 32, n0 = blockIdx.y * 32;
    const int tx = threadIdx.x, ty = threadIdx.y;
#pragma unroll
    for (int i = 0; i < 4; i++) {
        int kk = ty + 8 * i;
        s[kk][tx] = W2[(size_t)(k0 + kk) * CODE + n0 + tx];
    }
    __syncthreads();
#pragma unroll
    for (int i = 0; i < 4; i++) {
        int nn = ty + 8 * i;
        __half hi, lo;
        split2(s[tx][nn] * WSCALE, hi, lo);
        __half* row = g_w2h + (size_t)(n0 + nn) * K2_2;
        row[0 * H_DIM + k0 + tx] = hi;
        row[1 * H_DIM + k0 + tx] = lo;
    }
}

// ---------------------------------------------------------------------------
extern "C" void kernel_launch(void* const* d_in, const int* in_sizes, int n_in,
                              void* d_out, int out_size)
{
    const float* series   = (const float*)d_in[0];
    const float* gumbel_u = (const float*)d_in[1];
    const float* W1       = (const float*)d_in[2];
    const float* b1       = (const float*)d_in[3];
    const float* W2       = (const float*)d_in[4];
    const float* b2       = (const float*)d_in[5];
    const float* codebook = (const float*)d_in[6];
    float* out = (float*)d_out;

    cudaFuncSetAttribute(gemm1_mma, cudaFuncAttributeMaxDynamicSharedMemorySize, SMEM_DYN);
    cudaFuncSetAttribute(gemm2_mma, cudaFuncAttributeMaxDynamicSharedMemorySize, SMEM_DYN2);

    conv_x_kernel <<<dim3(FEAT_I / 32, T_ / 32, B_), dim3(32, 8)>>>(series);
    conv_w1_kernel<<<dim3(FEAT_I / 32, H_DIM / 32),  dim3(32, 8)>>>(W1);
    conv_w2_kernel<<<dim3(H_DIM / 32, CODE / 32),    dim3(32, 8)>>>(W2);

    gemm1_mma<<<dim3(H_DIM / 128, N_ / 128), 256, SMEM_DYN>>>(b1);
    gemm2_mma<<<dim3(CODE / 128,  N_ / 128), 256, SMEM_DYN2>>>(b2, gumbel_u);

    reset_count<<<1, 1>>>();
    argmax_margin_kernel<<<dim3(T_ / 32, B_, 2), 256>>>();
    refine_kernel<<<CAP / 4, 128>>>(b2, gumbel_u);
    gather_kernel<<<dim3(T_ / 32, B_, 2), 256>>>(codebook, out);
}

// round 17
// speedup vs baseline: 1.8779x; 1.0147x over previous
#include <cuda_runtime.h>
#include <cuda_fp16.h>
#include <math.h>
#include <stdint.h>

#define FEAT_I 512
#define H_DIM  1024
#define CODE   640
#define CODE_G 320
#define FEAT_G 256
#define B_     8
#define T_     4096
#define N_     (B_ * T_)                  // 32768
#define Q_ELEMS ((size_t)B_ * 512 * T_)   // 16,777,216

#define K2_1 (2 * FEAT_I)    // 1024
#define K2_2 (2 * H_DIM)     // 2048

#define WSCALE     64.0f
#define INV_WSCALE (1.0f / 64.0f)

// margin threshold: approx-logit error (1-term gemm2) max ~2e-3; 5x headroom
#define THR  0.01f
#define CAP  8192

// gemm1 smem: 2 bufs x (2 A-planes + 2 B-planes) x 8KB = 64KB
#define PLANE_SZ   8192
#define B_OFF      16384
#define BUF_STRIDE 32768
#define SMEM_DYN   65536
// gemm2 smem: 2 bufs x (A 8KB + B 8KB) = 32KB
#define SMEM_DYN2  32768

// ---------------------------------------------------------------------------
// Device scratch (allocation-free rule)
// ---------------------------------------------------------------------------
__device__ __half g_xh [(size_t)N_    * K2_1];  // x planes    [m][p*512+k]
__device__ __half g_w1h[(size_t)H_DIM * K2_1];  // (64*W1)^T   [n][p*512+k]
__device__ __half g_hh [(size_t)N_    * K2_2];  // h planes    [m][p*1024+k]
__device__ __half g_w2h[(size_t)CODE  * K2_2];  // (64*W2)^T   [n][p*1024+k]
__device__ float  g_logits[(size_t)N_ * CODE];  // approx perturbed logits
__device__ int    g_list[CAP];                  // uncertain (n*2+g) entries
__device__ int    g_count;

// ---------------------------------------------------------------------------
// PTX helpers (arch-agnostic sm_80-class)
// ---------------------------------------------------------------------------
__device__ __forceinline__ uint32_t smem_u32(const void* p) {
    uint32_t a;
    asm("{ .reg .u64 t; cvta.to.shared.u64 t, %1; cvt.u32.u64 %0, t; }" : "=r"(a) : "l"(p));
    return a;
}
__device__ __forceinline__ void cp16(uint32_t saddr, const void* g) {
    asm volatile("cp.async.cg.shared.global [%0], [%1], 16;" :: "r"(saddr), "l"(g));
}
#define CP_COMMIT() asm volatile("cp.async.commit_group;" ::: "memory")
#define CP_WAIT0()  asm volatile("cp.async.wait_group 0;" ::: "memory")
#define CP_WAIT1()  asm volatile("cp.async.wait_group 1;" ::: "memory")

__device__ __forceinline__ void ldsm4(uint32_t& a, uint32_t& b, uint32_t& c, uint32_t& d,
                                      uint32_t addr) {
    asm volatile("ldmatrix.sync.aligned.m8n8.x4.shared.b16 {%0,%1,%2,%3}, [%4];"
                 : "=r"(a), "=r"(b), "=r"(c), "=r"(d) : "r"(addr));
}
__device__ __forceinline__ void mma16816(float* d, const uint32_t* a, uint32_t b0, uint32_t b1) {
    asm volatile("mma.sync.aligned.m16n8k16.row.col.f32.f16.f16.f32 "
                 "{%0,%1,%2,%3},{%4,%5,%6,%7},{%8,%9},{%0,%1,%2,%3};"
                 : "+f"(d[0]), "+f"(d[1]), "+f"(d[2]), "+f"(d[3])
                 : "r"(a[0]), "r"(a[1]), "r"(a[2]), "r"(a[3]), "r"(b0), "r"(b1));
}

__device__ __forceinline__ void split2(float v, __half& hi, __half& lo) {
    hi = __float2half_rn(v);
    lo = __float2half_rn(v - __half2float(hi));
}
__device__ __forceinline__ uint32_t plane_swz(int r, int c) {
    return (uint32_t)(r * 64 + ((c ^ ((r >> 1) & 3)) * 16));
}
__device__ __forceinline__ float gumbelf(float u) {
    return -logf(-logf(u + 1e-10f) + 1e-10f);
}

// ---------------------------------------------------------------------------
// GEMM1 core (R13, proven): 128x128 block, 256 thr, 64x32 warp tiles,
// 3 cross terms over 2 fp16 planes, 2-ahead cp.async pipeline.
// ---------------------------------------------------------------------------
template<int KPLANE>
__device__ __forceinline__ void gemm_core3(const char* __restrict__ Abase,
                                           const char* __restrict__ Bbase,
                                           int tid, uint32_t smb,
                                           float acc[4][4][4]) {
    const int lane = tid & 31, wid = tid >> 5;
    const int warp_m = wid >> 2;     // 0..1
    const int warp_n = wid & 3;      // 0..3
    constexpr int KCH = KPLANE / 32;
    const size_t ROWB = (size_t)KPLANE * 4;   // 2 planes * 2 bytes

    const int cst = tid & 3;
    const int rst = tid >> 2;        // 0..63

    auto issue = [&](int kc, int buf) {
        const uint32_t base = smb + buf * BUF_STRIDE;
#pragma unroll
        for (int p = 0; p < 2; p++) {
            const size_t col = (size_t)(p * KPLANE + kc * 32) * 2 + cst * 16;
#pragma unroll
            for (int i = 0; i < 2; i++) {
                const int r = rst + 64 * i;
                const uint32_t so = plane_swz(r, cst);
                cp16(base + p * PLANE_SZ + so,         Abase + (size_t)r * ROWB + col);
                cp16(base + B_OFF + p * PLANE_SZ + so, Bbase + (size_t)r * ROWB + col);
            }
        }
    };

    issue(0, 0); CP_COMMIT();
    issue(1, 1); CP_COMMIT();

    for (int kc = 0; kc < KCH; kc++) {
        if (kc == KCH - 1) { CP_WAIT0(); } else { CP_WAIT1(); }
        __syncthreads();
        const uint32_t bufb = smb + (kc & 1) * BUF_STRIDE;
#pragma unroll
        for (int kk = 0; kk < 2; kk++) {
            const int lrow = lane & 15;
            const int ch = kk * 2 + (lane >> 4);
            uint32_t afr[4][4], bfr[2][4];

            auto loadA = [&](int pa) {
                const uint32_t bA = bufb + pa * PLANE_SZ;
#pragma unroll
                for (int im = 0; im < 4; im++) {
                    const int r = warp_m * 64 + im * 16 + lrow;
                    ldsm4(afr[im][0], afr[im][1], afr[im][2], afr[im][3],
                          bA + plane_swz(r, ch));
                }
            };
            auto loadB = [&](int pb) {
                const uint32_t bB = bufb + B_OFF + pb * PLANE_SZ;
#pragma unroll
                for (int i2 = 0; i2 < 2; i2++) {
                    const int r = warp_n * 32 + i2 * 16 + lrow;
                    ldsm4(bfr[i2][0], bfr[i2][1], bfr[i2][2], bfr[i2][3],
                          bB + plane_swz(r, ch));
                }
            };
            auto mmas = [&]() {
#pragma unroll
                for (int im = 0; im < 4; im++)
#pragma unroll
                    for (int in = 0; in < 4; in++)
                        mma16816(acc[im][in], afr[im],
                                 bfr[in >> 1][in & 1], bfr[in >> 1][(in & 1) + 2]);
            };

            loadA(0); loadB(0); mmas(); loadB(1); mmas();
            loadA(1); loadB(0); mmas();
        }
        __syncthreads();
        if (kc + 2 < KCH) { issue(kc + 2, kc & 1); CP_COMMIT(); }
    }
    __syncthreads();
}

// ---------------------------------------------------------------------------
// GEMM1: h = relu((x @ 64*W1)/64 + b1) -> split2 -> g_hh  (R13, proven)
// ---------------------------------------------------------------------------
__global__ __launch_bounds__(256, 2)
void gemm1_mma(const float* __restrict__ b1) {
    extern __shared__ char smem[];
    const uint32_t smb = smem_u32(smem);
    const int tid = threadIdx.x, lane = tid & 31, wid = tid >> 5;
    const int warp_m = wid >> 2, warp_n = wid & 3;
    const int jBase = blockIdx.x * 128;
    const int mBase = blockIdx.y * 128;

    float acc[4][4][4];
#pragma unroll
    for (int i = 0; i < 4; i++)
#pragma unroll
        for (int j = 0; j < 4; j++)
#pragma unroll
            for (int k = 0; k < 4; k++) acc[i][j][k] = 0.f;

    gemm_core3<FEAT_I>((const char*)(g_xh + (size_t)mBase * K2_1),
                       (const char*)(g_w1h + (size_t)jBase * K2_1), tid, smb, acc);

    float bv[4][2];
#pragma unroll
    for (int in = 0; in < 4; in++)
#pragma unroll
        for (int e = 0; e < 2; e++)
            bv[in][e] = __ldg(&b1[jBase + warp_n * 32 + in * 8 + (lane & 3) * 2 + e]);
#pragma unroll
    for (int im = 0; im < 4; im++)
#pragma unroll
        for (int in = 0; in < 4; in++)
#pragma unroll
            for (int q = 0; q < 4; q++) {
                float z = acc[im][in][q] * INV_WSCALE + bv[in][q & 1];
                acc[im][in][q] = z > 0.f ? z : 0.f;
            }

    __half* stage = (__half*)smem;
#pragma unroll
    for (int p = 0; p < 2; p++) {
#pragma unroll
        for (int im = 0; im < 4; im++)
#pragma unroll
            for (int in = 0; in < 4; in++)
#pragma unroll
                for (int rr = 0; rr < 2; rr++) {
                    const int r = warp_m * 64 + im * 16 + (lane >> 2) + rr * 8;
                    const int col = warp_n * 32 + in * 8 + (lane & 3) * 2;
                    __half2 v;
#pragma unroll
                    for (int e = 0; e < 2; e++) {
                        float z = acc[im][in][rr * 2 + e];
                        __half hp = __float2half_rn(z);
                        acc[im][in][rr * 2 + e] = z - __half2float(hp);
                        ((__half*)&v)[e] = hp;
                    }
                    *(__half2*)&stage[r * 128 + col] = v;
                }
        __syncthreads();
#pragma unroll
        for (int i = 0; i < 8; i++) {
            const int id = tid + 256 * i;
            const int r = id >> 4, c4 = id & 15;
            float4 v = *(const float4*)&stage[r * 128 + c4 * 8];
            *(float4*)&g_hh[(size_t)(mBase + r) * K2_2 + p * H_DIM + jBase + c4 * 8] = v;
        }
        __syncthreads();
    }
}

// ---------------------------------------------------------------------------
// GEMM2 (1-term approx, R13): logits ~= (h_hi @ 64*W2_hi)/64 + b2 + gumbel
// ---------------------------------------------------------------------------
__global__ __launch_bounds__(256, 2)
void gemm2_mma(const float* __restrict__ b2, const float* __restrict__ gumbel_u) {
    extern __shared__ char smem[];
    const uint32_t smb = smem_u32(smem);
    const int tid = threadIdx.x, lane = tid & 31, wid = tid >> 5;
    const int warp_m = wid >> 2, warp_n = wid & 3;
    const int jBase = blockIdx.x * 128;
    const int mBase = blockIdx.y * 128;

    const char* Abase = (const char*)(g_hh + (size_t)mBase * K2_2);   // plane 0
    const char* Bbase = (const char*)(g_w2h + (size_t)jBase * K2_2);  // plane 0
    const size_t ROWB = (size_t)K2_2 * 2;   // 4096 bytes

    float acc[4][4][4];
#pragma unroll
    for (int i = 0; i < 4; i++)
#pragma unroll
        for (int j = 0; j < 4; j++)
#pragma unroll
            for (int k = 0; k < 4; k++) acc[i][j][k] = 0.f;

    const int cst = tid & 3;
    const int rst = tid >> 2;    // 0..63
    auto issue = [&](int kc, int buf) {
        const uint32_t base = smb + buf * 16384;
        const size_t col = (size_t)kc * 64 + cst * 16;
#pragma unroll
        for (int i = 0; i < 2; i++) {
            const int r = rst + 64 * i;
            const uint32_t so = plane_swz(r, cst);
            cp16(base + so,        Abase + (size_t)r * ROWB + col);
            cp16(base + 8192 + so, Bbase + (size_t)r * ROWB + col);
        }
    };

    issue(0, 0); CP_COMMIT();
    issue(1, 1); CP_COMMIT();

    const int KCH = H_DIM / 32;   // 32
    for (int kc = 0; kc < KCH; kc++) {
        if (kc == KCH - 1) { CP_WAIT0(); } else { CP_WAIT1(); }
        __syncthreads();
        const uint32_t bufb = smb + (kc & 1) * 16384;
#pragma unroll
        for (int kk = 0; kk < 2; kk++) {
            const int lrow = lane & 15;
            const int ch = kk * 2 + (lane >> 4);
            uint32_t afr[4][4], bfr[2][4];
#pragma unroll
            for (int im = 0; im < 4; im++) {
                const int r = warp_m * 64 + im * 16 + lrow;
                ldsm4(afr[im][0], afr[im][1], afr[im][2], afr[im][3],
                      bufb + plane_swz(r, ch));
            }
#pragma unroll
            for (int i2 = 0; i2 < 2; i2++) {
                const int r = warp_n * 32 + i2 * 16 + lrow;
                ldsm4(bfr[i2][0], bfr[i2][1], bfr[i2][2], bfr[i2][3],
                      bufb + 8192 + plane_swz(r, ch));
            }
#pragma unroll
            for (int im = 0; im < 4; im++)
#pragma unroll
                for (int in = 0; in < 4; in++)
                    mma16816(acc[im][in], afr[im],
                             bfr[in >> 1][in & 1], bfr[in >> 1][(in & 1) + 2]);
        }
        __syncthreads();
        if (kc + 2 < KCH) { issue(kc + 2, kc & 1); CP_COMMIT(); }
    }
    __syncthreads();

    float bv[4][2];
#pragma unroll
    for (int in = 0; in < 4; in++)
#pragma unroll
        for (int e = 0; e < 2; e++)
            bv[in][e] = __ldg(&b2[jBase + warp_n * 32 + in * 8 + (lane & 3) * 2 + e]);

#pragma unroll
    for (int im = 0; im < 4; im++)
#pragma unroll
        for (int in = 0; in < 4; in++)
#pragma unroll
            for (int rr = 0; rr < 2; rr++) {
                const int m = mBase + warp_m * 64 + im * 16 + (lane >> 2) + rr * 8;
                const int j = jBase + warp_n * 32 + in * 8 + (lane & 3) * 2;
                const float2 u = *(const float2*)&gumbel_u[(size_t)m * CODE + j];
                float2 o;
                o.x = acc[im][in][rr * 2 + 0] * INV_WSCALE + bv[in][0] + gumbelf(u.x);
                o.y = acc[im][in][rr * 2 + 1] * INV_WSCALE + bv[in][1] + gumbelf(u.y);
                *(float2*)&g_logits[(size_t)m * CODE + j] = o;
            }
}

// ---------------------------------------------------------------------------
// Fused argmax + margin + gather (R13 bodies concatenated): per (tile,g)
// compute top-1 idx (first-index tiebreak) + top-2 value; list small-margin
// rows; write idx output and approx q rows immediately.
// ---------------------------------------------------------------------------
__global__ __launch_bounds__(256)
void argmax_gather_margin(const float* __restrict__ codebook,
                          float* __restrict__ out) {
    const int t0 = blockIdx.x * 32;
    const int b  = blockIdx.y;
    const int g  = blockIdx.z;
    const int tid = threadIdx.x, lane = tid & 31, w = tid >> 5;

    __shared__ int s_idx[32];

#pragma unroll
    for (int rr = 0; rr < 4; rr++) {
        const int tl = w * 4 + rr;
        const int n  = b * T_ + t0 + tl;
        const float* lp = g_logits + (size_t)n * CODE + g * CODE_G;
        float v1 = -INFINITY, v2 = -INFINITY;
        int   i1 = 0;
        for (int c = lane; c < CODE_G; c += 32) {
            float v = lp[c];
            if (v > v1) { v2 = v1; v1 = v; i1 = c; }
            else if (v > v2) { v2 = v; }
        }
#pragma unroll
        for (int off = 16; off; off >>= 1) {
            float ov1 = __shfl_down_sync(0xffffffffu, v1, off);
            int   oi1 = __shfl_down_sync(0xffffffffu, i1, off);
            float ov2 = __shfl_down_sync(0xffffffffu, v2, off);
            if (ov1 > v1 || (ov1 == v1 && oi1 < i1)) {
                v2 = fmaxf(fmaxf(v2, ov2), v1);
                v1 = ov1; i1 = oi1;
            } else {
                v2 = fmaxf(fmaxf(v2, ov2), ov1);
            }
        }
        if (lane == 0) {
            s_idx[tl] = i1;
            out[Q_ELEMS + (size_t)n * 2 + g] = (float)i1;
            if (v1 - v2 < THR) {
                int pos = atomicAdd(&g_count, 1);
                if (pos < CAP) g_list[pos] = n * 2 + g;
            }
        }
    }
    __syncthreads();

    const int tx = tid & 31, fy = tid >> 5;
    const int idx = s_idx[tx];
    const float* cbrow = codebook + ((size_t)g * CODE_G + idx) * FEAT_G;
    float* outb = out + ((size_t)b * 512 + g * FEAT_G) * T_ + t0;
    for (int f = fy; f < FEAT_G; f += 8)
        outb[(size_t)f * T_ + tx] = cbrow[f];
}

// ---------------------------------------------------------------------------
// Refine (R13, proven): one warp per uncertain entry; candidates = codes
// within 2*THR of the approx max; exact fp32 from stored hi+lo h and hi+lo
// W2; ascending-index strict-> tiebreak. Writes idx + q row directly.
// ---------------------------------------------------------------------------
__global__ __launch_bounds__(128)
void refine_kernel(const float* __restrict__ b2,
                   const float* __restrict__ gumbel_u,
                   const float* __restrict__ codebook,
                   float* __restrict__ out) {
    const int tid = threadIdx.x, lane = tid & 31, w = tid >> 5;
    const int cnt = min(g_count, CAP);
    const int widx = blockIdx.x * 4 + w;
    if (widx >= cnt) return;

    const int ent = g_list[widx];
    const int n = ent >> 1, g = ent & 1;

    const float* lp = g_logits + (size_t)n * CODE + g * CODE_G;
    float z[10];
#pragma unroll
    for (int j = 0; j < 10; j++) z[j] = lp[32 * j + lane];

    float v1 = -INFINITY;
#pragma unroll
    for (int j = 0; j < 10; j++) v1 = fmaxf(v1, z[j]);
#pragma unroll
    for (int off = 16; off; off >>= 1)
        v1 = fmaxf(v1, __shfl_xor_sync(0xffffffffu, v1, off));
    const float thresh = v1 - 2.0f * THR;

    // preload h (hi+lo reconstructed fp32); lane owns k = 2*lane + 64*jj
    float2 hv[16];
    const __half* hr = g_hh + (size_t)n * K2_2;
#pragma unroll
    for (int jj = 0; jj < 16; jj++) {
        const int k = 2 * lane + 64 * jj;
        __half2 hi = *(const __half2*)&hr[k];
        __half2 lo = *(const __half2*)&hr[H_DIM + k];
        hv[jj].x = __half2float(hi.x) + __half2float(lo.x);
        hv[jj].y = __half2float(hi.y) + __half2float(lo.y);
    }

    float best = -INFINITY;
    int   bidx = 0;
    for (int j = 0; j < 10; j++) {
        unsigned bits = __ballot_sync(0xffffffffu, z[j] >= thresh);
        while (bits) {
            const int i = __ffs(bits) - 1;
            bits &= bits - 1;
            const int c = 32 * j + i;                 // ascending
            const __half* wrow = g_w2h + (size_t)(g * CODE_G + c) * K2_2;
            float a = 0.f;
#pragma unroll
            for (int jj = 0; jj < 16; jj++) {
                const int k = 2 * lane + 64 * jj;
                __half2 hi = *(const __half2*)&wrow[k];
                __half2 lo = *(const __half2*)&wrow[H_DIM + k];
                a += hv[jj].x * (__half2float(hi.x) + __half2float(lo.x))
                   + hv[jj].y * (__half2float(hi.y) + __half2float(lo.y));
            }
#pragma unroll
            for (int off = 16; off; off >>= 1)
                a += __shfl_xor_sync(0xffffffffu, a, off);
            const int col = g * CODE_G + c;
            const float z_ex = a * INV_WSCALE + b2[col]
                               + gumbelf(gumbel_u[(size_t)n * CODE + col]);
            if (z_ex > best) { best = z_ex; bidx = c; }
        }
    }

    // write final idx + q row (overwrites the approx row; deterministic)
    const int bb = n >> 12, tt = n & 4095;
    if (lane == 0) out[Q_ELEMS + (size_t)n * 2 + g] = (float)bidx;
    const float* cbrow = codebook + ((size_t)g * CODE_G + bidx) * FEAT_G;
    float* outb = out + ((size_t)bb * 512 + g * FEAT_G) * T_ + tt;
    for (int f = lane; f < FEAT_G; f += 32)
        outb[(size_t)f * T_] = cbrow[f];
}

// ---------------------------------------------------------------------------
// Conversion kernels (tiled transpose + 2-plane fp16 split; R13)
// ---------------------------------------------------------------------------
__global__ __launch_bounds__(256)
void conv_x_kernel(const float* __restrict__ series) {
    __shared__ float s[32][33];
    const int k0 = blockIdx.x * 32, t0 = blockIdx.y * 32, b = blockIdx.z;
    const int tx = threadIdx.x, ty = threadIdx.y;
#pragma unroll
    for (int i = 0; i < 4; i++) {
        int kk = ty + 8 * i;
        s[kk][tx] = series[((size_t)b * FEAT_I + k0 + kk) * T_ + t0 + tx];
    }
    __syncthreads();
#pragma unroll
    for (int i = 0; i < 4; i++) {
        int tt = ty + 8 * i;
        int m = b * T_ + t0 + tt;
        __half hi, lo;
        split2(s[tx][tt], hi, lo);
        __half* row = g_xh + (size_t)m * K2_1;
        row[0 * FEAT_I + k0 + tx] = hi;
        row[1 * FEAT_I + k0 + tx] = lo;
    }
}

__global__ __launch_bounds__(256)
void conv_w1_kernel(const float* __restrict__ W1) {
    __shared__ float s[32][33];
    const int k0 = blockIdx.x * 32, n0 = blockIdx.y * 32;
    const int tx = threadIdx.x, ty = threadIdx.y;
    if (blockIdx.x == 0 && blockIdx.y == 0 && tx == 0 && ty == 0)
        g_count = 0;                       // reset for this replay
#pragma unroll
    for (int i = 0; i < 4; i++) {
        int kk = ty + 8 * i;
        s[kk][tx] = W1[(size_t)(k0 + kk) * H_DIM + n0 + tx];
    }
    __syncthreads();
#pragma unroll
    for (int i = 0; i < 4; i++) {
        int nn = ty + 8 * i;
        __half hi, lo;
        split2(s[tx][nn] * WSCALE, hi, lo);
        __half* row = g_w1h + (size_t)(n0 + nn) * K2_1;
        row[0 * FEAT_I + k0 + tx] = hi;
        row[1 * FEAT_I + k0 + tx] = lo;
    }
}

__global__ __launch_bounds__(256)
void conv_w2_kernel(const float* __restrict__ W2) {
    __shared__ float s[32][33];
    const int k0 = blockIdx.x * 32, n0 = blockIdx.y * 32;
    const int tx = threadIdx.x, ty = threadIdx.y;
#pragma unroll
    for (int i = 0; i < 4; i++) {
        int kk = ty + 8 * i;
        s[kk][tx] = W2[(size_t)(k0 + kk) * CODE + n0 + tx];
    }
    __syncthreads();
#pragma unroll
    for (int i = 0; i < 4; i++) {
        int nn = ty + 8 * i;
        __half hi, lo;
        split2(s[tx][nn] * WSCALE, hi, lo);
        __half* row = g_w2h + (size_t)(n0 + nn) * K2_2;
        row[0 * H_DIM + k0 + tx] = hi;
        row[1 * H_DIM + k0 + tx] = lo;
    }
}

// ---------------------------------------------------------------------------
extern "C" void kernel_launch(void* const* d_in, const int* in_sizes, int n_in,
                              void* d_out, int out_size)
{
    const float* series   = (const float*)d_in[0];
    const float* gumbel_u = (const float*)d_in[1];
    const float* W1       = (const float*)d_in[2];
    const float* b1       = (const float*)d_in[3];
    const float* W2       = (const float*)d_in[4];
    const float* b2       = (const float*)d_in[5];
    const float* codebook = (const float*)d_in[6];
    float* out = (float*)d_out;

    cudaFuncSetAttribute(gemm1_mma, cudaFuncAttributeMaxDynamicSharedMemorySize, SMEM_DYN);
    cudaFuncSetAttribute(gemm2_mma, cudaFuncAttributeMaxDynamicSharedMemorySize, SMEM_DYN2);

    conv_x_kernel <<<dim3(FEAT_I / 32, T_ / 32, B_), dim3(32, 8)>>>(series);
    conv_w1_kernel<<<dim3(FEAT_I / 32, H_DIM / 32),  dim3(32, 8)>>>(W1);
    conv_w2_kernel<<<dim3(H_DIM / 32, CODE / 32),    dim3(32, 8)>>>(W2);

    gemm1_mma<<<dim3(H_DIM / 128, N_ / 128), 256, SMEM_DYN>>>(b1);
    gemm2_mma<<<dim3(CODE / 128,  N_ / 128), 256, SMEM_DYN2>>>(b2, gumbel_u);

    argmax_gather_margin<<<dim3(T_ / 32, B_, 2), 256>>>(codebook, out);
    refine_kernel<<<CAP / 4, 128>>>(b2, gumbel_u, codebook, out);
}